// round 14
// baseline (speedup 1.0000x reference)
#include <cuda_runtime.h>
#include <cuda_fp16.h>
#include <mma.h>
#include <cstddef>
#include <cstdint>

using namespace nvcuda;

#define N_NODES   100000
#define N_EDGES   50000
#define N_INC     3200000
#define D_IN      128
#define D_HID     32
#define N_CLASSES 40

// ---------------------------------------------------------------------------
// Scratch (static device globals). Intermediate feature tables in fp16.
// ---------------------------------------------------------------------------
__device__ __half g_xw[(size_t)N_NODES * D_HID];
__device__ __half g_ef[(size_t)N_EDGES * D_HID];
__device__ __half g_h1[(size_t)N_NODES * D_HID];
__device__ float g_dinv[N_NODES];
__device__ float g_binv[N_EDGES];

__device__ int g_cnt_n[N_NODES];
__device__ int g_cnt_e[N_EDGES];
__device__ int g_off_n[N_NODES + 1];
__device__ int g_off_e[N_EDGES + 1];
__device__ int g_adj_n[N_INC];
__device__ int g_adj_e[N_INC];
__device__ unsigned short g_rank_n[N_INC];
__device__ unsigned short g_rank_e[N_INC];
__device__ int g_aux_n[128];
__device__ int g_aux_e[128];

#define NB_N ((N_NODES + 1023) / 1024)   // 98
#define NB_E ((N_EDGES + 1023) / 1024)   // 49

// ---------------------------------------------------------------------------
// GEMM1 (wmma tensor-core): Y[N,32](fp16) = X[N,128](fp32->fp16) @ W1(fp16).
// Also zeroes the degree counters (runs first).
// ---------------------------------------------------------------------------
#define G_TR   256
#define G_XLD  136                                     // halves/row, mult of 8
#define G_SMEM (D_IN * D_HID * 2 + G_TR * G_XLD * 2)   // 77824 B

__global__ void gemm1_kernel(const float* __restrict__ X,
                             const float* __restrict__ W,
                             __half* __restrict__ Y, int N,
                             int* __restrict__ cn, int* __restrict__ ce) {
    extern __shared__ __align__(16) char smemraw[];
    __half* ws = (__half*)smemraw;                     // 128x32
    __half* xs = (__half*)(smemraw + 8192);            // 256x136
    float*  ys = (float*)(smemraw + 8192);             // alias, post-compute
    const int tid  = threadIdx.x;
    const int warp = tid >> 5;

    for (int i = blockIdx.x * blockDim.x + tid; i < N_NODES; i += gridDim.x * blockDim.x)
        cn[i] = 0;
    for (int i = blockIdx.x * blockDim.x + tid; i < N_EDGES; i += gridDim.x * blockDim.x)
        ce[i] = 0;

    for (int i = tid; i < (D_IN * D_HID) / 4; i += 256) {
        float4 w = ((const float4*)W)[i];
        __half2 h0 = __float22half2_rn(make_float2(w.x, w.y));
        __half2 h1 = __float22half2_rn(make_float2(w.z, w.w));
        *(uint2*)(ws + i * 4) = make_uint2(*(uint32_t*)&h0, *(uint32_t*)&h1);
    }
    const int row0 = blockIdx.x * G_TR;
    for (int i = tid; i < G_TR * (D_IN / 4); i += 256) {
        int r = i >> 5, c = i & 31;
        float4 v = make_float4(0.f, 0.f, 0.f, 0.f);
        if (row0 + r < N) v = ((const float4*)X)[(size_t)(row0 + r) * (D_IN / 4) + c];
        __half2 h0 = __float22half2_rn(make_float2(v.x, v.y));
        __half2 h1 = __float22half2_rn(make_float2(v.z, v.w));
        *(uint2*)(xs + r * G_XLD + c * 4) = make_uint2(*(uint32_t*)&h0, *(uint32_t*)&h1);
    }
    __syncthreads();

    wmma::fragment<wmma::accumulator, 16, 16, 16, float> acc00, acc01, acc10, acc11;
    wmma::fill_fragment(acc00, 0.f); wmma::fill_fragment(acc01, 0.f);
    wmma::fill_fragment(acc10, 0.f); wmma::fill_fragment(acc11, 0.f);

    const __half* a0 = xs + (32 * warp) * G_XLD;
    const __half* a1 = xs + (32 * warp + 16) * G_XLD;
#pragma unroll
    for (int k = 0; k < D_IN; k += 16) {
        wmma::fragment<wmma::matrix_a, 16, 16, 16, __half, wmma::row_major> fa0, fa1;
        wmma::fragment<wmma::matrix_b, 16, 16, 16, __half, wmma::row_major> fb0, fb1;
        wmma::load_matrix_sync(fa0, a0 + k, G_XLD);
        wmma::load_matrix_sync(fa1, a1 + k, G_XLD);
        wmma::load_matrix_sync(fb0, ws + k * D_HID, D_HID);
        wmma::load_matrix_sync(fb1, ws + k * D_HID + 16, D_HID);
        wmma::mma_sync(acc00, fa0, fb0, acc00);
        wmma::mma_sync(acc01, fa0, fb1, acc01);
        wmma::mma_sync(acc10, fa1, fb0, acc10);
        wmma::mma_sync(acc11, fa1, fb1, acc11);
    }
    __syncthreads();

    wmma::store_matrix_sync(ys + (32 * warp) * 32,           acc00, 32, wmma::mem_row_major);
    wmma::store_matrix_sync(ys + (32 * warp) * 32 + 16,      acc01, 32, wmma::mem_row_major);
    wmma::store_matrix_sync(ys + (32 * warp + 16) * 32,      acc10, 32, wmma::mem_row_major);
    wmma::store_matrix_sync(ys + (32 * warp + 16) * 32 + 16, acc11, 32, wmma::mem_row_major);
    __syncthreads();

    for (int i = tid; i < G_TR * 8; i += 256) {
        int r = i >> 3, c4 = i & 7;
        const int row = row0 + r;
        if (row < N) {
            float4 v = *(const float4*)(ys + r * 32 + c4 * 4);
            __half2 h0 = __float22half2_rn(make_float2(v.x, v.y));
            __half2 h1 = __float22half2_rn(make_float2(v.z, v.w));
            *(uint2*)(Y + (size_t)row * D_HID + c4 * 4) =
                make_uint2(*(uint32_t*)&h0, *(uint32_t*)&h1);
        }
    }
}

// ---------------------------------------------------------------------------
// Degree counting + per-pair rank capture (u16 ranks)
// ---------------------------------------------------------------------------
__global__ void degree_rank_kernel(const int* __restrict__ nidx,
                                   const int* __restrict__ eidx,
                                   int* __restrict__ cn, int* __restrict__ ce,
                                   unsigned short* __restrict__ rank_n,
                                   unsigned short* __restrict__ rank_e, int n) {
    int i = blockIdx.x * blockDim.x + threadIdx.x;
    if (i < n) {
        rank_n[i] = (unsigned short)atomicAdd(cn + nidx[i], 1);
        rank_e[i] = (unsigned short)atomicAdd(ce + eidx[i], 1);
    }
}

// ---------------------------------------------------------------------------
// Combined block scan + fused 1/deg
// ---------------------------------------------------------------------------
__global__ void scan_block2(const int* __restrict__ cnt_n, int* __restrict__ off_n,
                            int* __restrict__ aux_n, float* __restrict__ dinv,
                            const int* __restrict__ cnt_e, int* __restrict__ off_e,
                            int* __restrict__ aux_e, float* __restrict__ binv) {
    __shared__ int sm[1024];
    const int b = blockIdx.x;
    const int* in;  int* out; int* aux; float* inv; int n; int bb;
    if (b < NB_N) { in = cnt_n; out = off_n; aux = aux_n; inv = dinv; n = N_NODES; bb = b; }
    else          { in = cnt_e; out = off_e; aux = aux_e; inv = binv; n = N_EDGES; bb = b - NB_N; }

    const int tid = threadIdx.x;
    const int i = bb * 1024 + tid;
    int v = (i < n) ? in[i] : 0;
    if (i < n) inv[i] = (v > 0) ? (1.0f / (float)v) : 0.0f;
    sm[tid] = v;
    __syncthreads();
#pragma unroll
    for (int o = 1; o < 1024; o <<= 1) {
        int t = (tid >= o) ? sm[tid - o] : 0;
        __syncthreads();
        sm[tid] += t;
        __syncthreads();
    }
    if (i < n) out[i] = sm[tid] - v;
    if (tid == 1023) aux[bb] = sm[1023];
}

// Add-pass with inline aux scan (each block redundantly scans the aux array).
__global__ void scan_add2(int* __restrict__ off_n, const int* __restrict__ aux_n,
                          int* __restrict__ off_e, const int* __restrict__ aux_e) {
    __shared__ int sm[128];
    const int b = blockIdx.x;
    const int t = threadIdx.x;
    const int* aux; int* off; int n; int bb; int nb;
    if (b < NB_N) { aux = aux_n; off = off_n; n = N_NODES; bb = b; nb = NB_N; }
    else          { aux = aux_e; off = off_e; n = N_EDGES; bb = b - NB_N; nb = NB_E; }

    if (t < 128) sm[t] = (t < nb) ? aux[t] : 0;
    __syncthreads();
#pragma unroll
    for (int o = 1; o < 128; o <<= 1) {
        int v = (t < 128 && t >= o) ? sm[t - o] : 0;
        __syncthreads();
        if (t < 128) sm[t] += v;
        __syncthreads();
    }
    const int add = (bb == 0) ? 0 : sm[bb - 1];
    const int i = bb * 1024 + t;
    if (i < n) off[i] += add;
    if (i == 0 && bb == 0) off[n] = N_INC;
}

// ---------------------------------------------------------------------------
// CSR fill — atomic-free via precomputed u16 ranks
// ---------------------------------------------------------------------------
__global__ void fill_csr(const int* __restrict__ nidx, const int* __restrict__ eidx,
                         const int* __restrict__ off_n, const int* __restrict__ off_e,
                         const unsigned short* __restrict__ rank_n,
                         const unsigned short* __restrict__ rank_e,
                         int* __restrict__ adj_n, int* __restrict__ adj_e, int n) {
    int i = blockIdx.x * blockDim.x + threadIdx.x;
    if (i < n) {
        int v = nidx[i], e = eidx[i];
        adj_n[__ldg(off_n + v) + (int)rank_n[i]] = e;
        adj_e[__ldg(off_e + e) + (int)rank_e[i]] = v;
    }
}

// ---------------------------------------------------------------------------
// fp16 CSR gather, MLP-4 main loop (32 members/iter).
// lane -> (member slot r = lane>>2, quad q = lane&3); fp32 accumulate.
// MODE 0: dst = half(scale*sum)   MODE 1: dst = half(relu(scale*sum + bias))
// ---------------------------------------------------------------------------
__device__ __forceinline__ void acc8(float2 a[4], uint4 v) {
    float2 f0 = __half22float2(*(const __half2*)&v.x);
    float2 f1 = __half22float2(*(const __half2*)&v.y);
    float2 f2 = __half22float2(*(const __half2*)&v.z);
    float2 f3 = __half22float2(*(const __half2*)&v.w);
    a[0].x += f0.x; a[0].y += f0.y;
    a[1].x += f1.x; a[1].y += f1.y;
    a[2].x += f2.x; a[2].y += f2.y;
    a[3].x += f3.x; a[3].y += f3.y;
}

template <int MODE>
__global__ void gather_kernel(const int* __restrict__ off,
                              const int* __restrict__ adj,
                              const __half* __restrict__ src,
                              const float* __restrict__ scale,
                              const float* __restrict__ bias,
                              __half* __restrict__ dst, int nrows) {
    const int row  = (blockIdx.x * blockDim.x + threadIdx.x) >> 5;
    const int lane = threadIdx.x & 31;
    if (row >= nrows) return;
    const int r = lane >> 2;
    const int q = lane & 3;

    const int s = off[row], e = off[row + 1];
    float2 a[4] = {{0.f,0.f},{0.f,0.f},{0.f,0.f},{0.f,0.f}};
    int j = s;
    for (; j + 32 <= e; j += 32) {                    // 4 independent chains
        int m0 = adj[j + r];
        int m1 = adj[j + 8 + r];
        int m2 = adj[j + 16 + r];
        int m3 = adj[j + 24 + r];
        uint4 v0 = *(const uint4*)(src + (size_t)m0 * D_HID + q * 8);
        uint4 v1 = *(const uint4*)(src + (size_t)m1 * D_HID + q * 8);
        uint4 v2 = *(const uint4*)(src + (size_t)m2 * D_HID + q * 8);
        uint4 v3 = *(const uint4*)(src + (size_t)m3 * D_HID + q * 8);
        acc8(a, v0); acc8(a, v1); acc8(a, v2); acc8(a, v3);
    }
    for (; j + 16 <= e; j += 16) {
        int m0 = adj[j + r];
        int m1 = adj[j + 8 + r];
        uint4 v0 = *(const uint4*)(src + (size_t)m0 * D_HID + q * 8);
        uint4 v1 = *(const uint4*)(src + (size_t)m1 * D_HID + q * 8);
        acc8(a, v0); acc8(a, v1);
    }
    for (; j < e; j += 8) {
        if (j + r < e) {
            int m = adj[j + r];
            uint4 v = *(const uint4*)(src + (size_t)m * D_HID + q * 8);
            acc8(a, v);
        }
    }
#pragma unroll
    for (int o = 4; o <= 16; o <<= 1) {
#pragma unroll
        for (int i = 0; i < 4; i++) {
            a[i].x += __shfl_xor_sync(0xffffffffu, a[i].x, o);
            a[i].y += __shfl_xor_sync(0xffffffffu, a[i].y, o);
        }
    }

    if (r == 0) {
        const float f = scale[row];
        uint4 pk;
        if (MODE == 0) {
            __half2 h0 = __float22half2_rn(make_float2(a[0].x * f, a[0].y * f));
            __half2 h1 = __float22half2_rn(make_float2(a[1].x * f, a[1].y * f));
            __half2 h2 = __float22half2_rn(make_float2(a[2].x * f, a[2].y * f));
            __half2 h3 = __float22half2_rn(make_float2(a[3].x * f, a[3].y * f));
            pk = make_uint4(*(uint32_t*)&h0, *(uint32_t*)&h1,
                            *(uint32_t*)&h2, *(uint32_t*)&h3);
        } else {
            float4 b0 = *(const float4*)(bias + q * 8);
            float4 b1 = *(const float4*)(bias + q * 8 + 4);
            float z0 = fmaxf(a[0].x * f + b0.x, 0.f);
            float z1 = fmaxf(a[0].y * f + b0.y, 0.f);
            float z2 = fmaxf(a[1].x * f + b0.z, 0.f);
            float z3 = fmaxf(a[1].y * f + b0.w, 0.f);
            float z4 = fmaxf(a[2].x * f + b1.x, 0.f);
            float z5 = fmaxf(a[2].y * f + b1.y, 0.f);
            float z6 = fmaxf(a[3].x * f + b1.z, 0.f);
            float z7 = fmaxf(a[3].y * f + b1.w, 0.f);
            __half2 h0 = __float22half2_rn(make_float2(z0, z1));
            __half2 h1 = __float22half2_rn(make_float2(z2, z3));
            __half2 h2 = __float22half2_rn(make_float2(z4, z5));
            __half2 h3 = __float22half2_rn(make_float2(z6, z7));
            pk = make_uint4(*(uint32_t*)&h0, *(uint32_t*)&h1,
                            *(uint32_t*)&h2, *(uint32_t*)&h3);
        }
        *(uint4*)(dst + (size_t)row * D_HID + q * 8) = pk;
    }
}

// ---------------------------------------------------------------------------
// Fused final: fp16 node-gather (MLP-4) + @W2 [32,40] + b2 + log_softmax.
// ---------------------------------------------------------------------------
__global__ void gather_w2_logsoftmax(const int* __restrict__ off,
                                     const int* __restrict__ adj,
                                     const __half* __restrict__ src,
                                     const float* __restrict__ dinv,
                                     const float* __restrict__ W2,
                                     const float* __restrict__ b2,
                                     float* __restrict__ out, int nrows) {
    __shared__ float w2s[D_HID * N_CLASSES];
    __shared__ float b2s[N_CLASSES];
    {
        const int t = threadIdx.x;
        for (int i = t; i < D_HID * N_CLASSES; i += blockDim.x) w2s[i] = W2[i];
        if (t < N_CLASSES) b2s[t] = b2[t];
    }
    __syncthreads();

    const int row  = (blockIdx.x * blockDim.x + threadIdx.x) >> 5;
    const int lane = threadIdx.x & 31;
    if (row >= nrows) return;
    const int r = lane >> 2;
    const int q = lane & 3;

    const int s = off[row], e = off[row + 1];
    float2 a[4] = {{0.f,0.f},{0.f,0.f},{0.f,0.f},{0.f,0.f}};
    int j = s;
    for (; j + 32 <= e; j += 32) {
        int m0 = adj[j + r];
        int m1 = adj[j + 8 + r];
        int m2 = adj[j + 16 + r];
        int m3 = adj[j + 24 + r];
        uint4 v0 = *(const uint4*)(src + (size_t)m0 * D_HID + q * 8);
        uint4 v1 = *(const uint4*)(src + (size_t)m1 * D_HID + q * 8);
        uint4 v2 = *(const uint4*)(src + (size_t)m2 * D_HID + q * 8);
        uint4 v3 = *(const uint4*)(src + (size_t)m3 * D_HID + q * 8);
        acc8(a, v0); acc8(a, v1); acc8(a, v2); acc8(a, v3);
    }
    for (; j + 16 <= e; j += 16) {
        int m0 = adj[j + r];
        int m1 = adj[j + 8 + r];
        uint4 v0 = *(const uint4*)(src + (size_t)m0 * D_HID + q * 8);
        uint4 v1 = *(const uint4*)(src + (size_t)m1 * D_HID + q * 8);
        acc8(a, v0); acc8(a, v1);
    }
    for (; j < e; j += 8) {
        if (j + r < e) {
            int m = adj[j + r];
            uint4 v = *(const uint4*)(src + (size_t)m * D_HID + q * 8);
            acc8(a, v);
        }
    }
#pragma unroll
    for (int o = 4; o <= 16; o <<= 1) {
#pragma unroll
        for (int i = 0; i < 4; i++) {
            a[i].x += __shfl_xor_sync(0xffffffffu, a[i].x, o);
            a[i].y += __shfl_xor_sync(0xffffffffu, a[i].y, o);
        }
    }

    const float di = dinv[row];
#pragma unroll
    for (int i = 0; i < 4; i++) { a[i].x *= di; a[i].y *= di; }

    float z0 = 0.f, z1 = 0.f;
#pragma unroll
    for (int k = 0; k < D_HID; k++) {
        const int idx = k & 7;
        float comp = (idx & 1) ? a[idx >> 1].y : a[idx >> 1].x;
        float ak = __shfl_sync(0xffffffffu, comp, k >> 3);
        z0 += ak * w2s[k * N_CLASSES + lane];
        if (lane < N_CLASSES - 32) z1 += ak * w2s[k * N_CLASSES + 32 + lane];
    }
    z0 += b2s[lane];
    z1 = (lane < N_CLASSES - 32) ? (z1 + b2s[32 + lane]) : -1e30f;

    float m = fmaxf(z0, z1);
#pragma unroll
    for (int o = 16; o; o >>= 1) m = fmaxf(m, __shfl_xor_sync(0xffffffffu, m, o));
    float ex = __expf(z0 - m) + ((lane < N_CLASSES - 32) ? __expf(z1 - m) : 0.f);
#pragma unroll
    for (int o = 16; o; o >>= 1) ex += __shfl_xor_sync(0xffffffffu, ex, o);
    const float lse = __logf(ex) + m;

    out[(size_t)row * N_CLASSES + lane] = z0 - lse;
    if (lane < N_CLASSES - 32)
        out[(size_t)row * N_CLASSES + 32 + lane] = z1 - lse;
}

// ---------------------------------------------------------------------------
// Launch — 9 kernels
// ---------------------------------------------------------------------------
extern "C" void kernel_launch(void* const* d_in, const int* in_sizes, int n_in,
                              void* d_out, int out_size) {
    const float* x    = (const float*)d_in[0];
    const int*   nidx = (const int*)d_in[1];
    const int*   eidx = (const int*)d_in[2];
    const float* W1   = (const float*)d_in[3];
    const float* b1   = (const float*)d_in[4];
    const float* W2   = (const float*)d_in[5];
    const float* b2   = (const float*)d_in[6];
    float* out = (float*)d_out;

    __half *xw, *ef, *h1;
    float *dinv, *binv;
    int *cnt_n, *cnt_e, *off_n, *off_e, *adj_n, *adj_e, *aux_n, *aux_e;
    unsigned short *rank_n, *rank_e;
    cudaGetSymbolAddress((void**)&xw,     g_xw);
    cudaGetSymbolAddress((void**)&ef,     g_ef);
    cudaGetSymbolAddress((void**)&h1,     g_h1);
    cudaGetSymbolAddress((void**)&dinv,   g_dinv);
    cudaGetSymbolAddress((void**)&binv,   g_binv);
    cudaGetSymbolAddress((void**)&cnt_n,  g_cnt_n);
    cudaGetSymbolAddress((void**)&cnt_e,  g_cnt_e);
    cudaGetSymbolAddress((void**)&off_n,  g_off_n);
    cudaGetSymbolAddress((void**)&off_e,  g_off_e);
    cudaGetSymbolAddress((void**)&adj_n,  g_adj_n);
    cudaGetSymbolAddress((void**)&adj_e,  g_adj_e);
    cudaGetSymbolAddress((void**)&rank_n, g_rank_n);
    cudaGetSymbolAddress((void**)&rank_e, g_rank_e);
    cudaGetSymbolAddress((void**)&aux_n,  g_aux_n);
    cudaGetSymbolAddress((void**)&aux_e,  g_aux_e);

    cudaFuncSetAttribute(gemm1_kernel,
                         cudaFuncAttributeMaxDynamicSharedMemorySize, G_SMEM);

    // 1: gemm1 (also zeros degree counters)
    gemm1_kernel<<<(N_NODES + G_TR - 1) / G_TR, 256, G_SMEM>>>(x, W1, xw, N_NODES,
                                                               cnt_n, cnt_e);
    // 2-5: degrees + CSR build
    degree_rank_kernel<<<(N_INC + 255) / 256, 256>>>(nidx, eidx, cnt_n, cnt_e,
                                                     rank_n, rank_e, N_INC);
    scan_block2<<<NB_N + NB_E, 1024>>>(cnt_n, off_n, aux_n, dinv,
                                       cnt_e, off_e, aux_e, binv);
    scan_add2<<<NB_N + NB_E, 1024>>>(off_n, aux_n, off_e, aux_e);
    fill_csr<<<(N_INC + 255) / 256, 256>>>(nidx, eidx, off_n, off_e,
                                           rank_n, rank_e, adj_n, adj_e, N_INC);

    // 6-7: layer 1
    gather_kernel<0><<<(N_EDGES + 7) / 8, 256>>>(off_e, adj_e, xw, binv, nullptr, ef, N_EDGES);
    gather_kernel<1><<<(N_NODES + 7) / 8, 256>>>(off_n, adj_n, ef, dinv, b1, h1, N_NODES);

    // 8-9: layer 2 (aggregate in hidden space; W2 post-aggregation)
    gather_kernel<0><<<(N_EDGES + 7) / 8, 256>>>(off_e, adj_e, h1, binv, nullptr, ef, N_EDGES);
    gather_w2_logsoftmax<<<(N_NODES + 7) / 8, 256>>>(off_n, adj_n, ef, dinv, W2, b2, out, N_NODES);
}

// round 17
// speedup vs baseline: 1.0151x; 1.0151x over previous
#include <cuda_runtime.h>
#include <cuda_fp16.h>
#include <mma.h>
#include <cstddef>
#include <cstdint>

using namespace nvcuda;

#define N_NODES   100000
#define N_EDGES   50000
#define N_INC     3200000
#define D_IN      128
#define D_HID     32
#define N_CLASSES 40

// ---------------------------------------------------------------------------
// Scratch (static device globals). Intermediate feature tables in fp16.
// Degree counters are zero at module load and re-zeroed by the FINAL kernel
// of each call, so every invocation (correctness, capture, replays) sees them
// zeroed — deterministic without a dedicated memset.
// ---------------------------------------------------------------------------
__device__ __half g_xw[(size_t)N_NODES * D_HID];
__device__ __half g_ef[(size_t)N_EDGES * D_HID];
__device__ __half g_h1[(size_t)N_NODES * D_HID];
__device__ float g_dinv[N_NODES];
__device__ float g_binv[N_EDGES];

__device__ int g_cnt_n[N_NODES];
__device__ int g_cnt_e[N_EDGES];
__device__ int g_off_n[N_NODES + 1];
__device__ int g_off_e[N_EDGES + 1];
__device__ unsigned short g_adj_n[N_INC];   // edge ids (<65536) grouped by node
__device__ int g_adj_e[N_INC];              // node ids grouped by edge
__device__ unsigned short g_rank_n[N_INC];
__device__ unsigned short g_rank_e[N_INC];
__device__ int g_aux_n[128];
__device__ int g_aux_e[128];

#define NB_N ((N_NODES + 1023) / 1024)   // 98
#define NB_E ((N_EDGES + 1023) / 1024)   // 49

// ---------------------------------------------------------------------------
// GEMM1 (wmma): Y[N,32](fp16) = X[N,128](fp32->fp16) @ W1(fp16).
// ---------------------------------------------------------------------------
#define G_TR   256
#define G_XLD  136
#define G_SMEM (D_IN * D_HID * 2 + G_TR * G_XLD * 2)   // 77824 B

__global__ void gemm1_kernel(const float* __restrict__ X,
                             const float* __restrict__ W,
                             __half* __restrict__ Y, int N) {
    extern __shared__ __align__(16) char smemraw[];
    __half* ws = (__half*)smemraw;                     // 128x32
    __half* xs = (__half*)(smemraw + 8192);            // 256x136
    float*  ys = (float*)(smemraw + 8192);             // alias post-compute
    const int tid  = threadIdx.x;
    const int warp = tid >> 5;

    for (int i = tid; i < (D_IN * D_HID) / 4; i += 256) {
        float4 w = ((const float4*)W)[i];
        __half2 h0 = __float22half2_rn(make_float2(w.x, w.y));
        __half2 h1 = __float22half2_rn(make_float2(w.z, w.w));
        *(uint2*)(ws + i * 4) = make_uint2(*(uint32_t*)&h0, *(uint32_t*)&h1);
    }
    const int row0 = blockIdx.x * G_TR;
    for (int i = tid; i < G_TR * (D_IN / 4); i += 256) {
        int r = i >> 5, c = i & 31;
        float4 v = make_float4(0.f, 0.f, 0.f, 0.f);
        if (row0 + r < N) v = ((const float4*)X)[(size_t)(row0 + r) * (D_IN / 4) + c];
        __half2 h0 = __float22half2_rn(make_float2(v.x, v.y));
        __half2 h1 = __float22half2_rn(make_float2(v.z, v.w));
        *(uint2*)(xs + r * G_XLD + c * 4) = make_uint2(*(uint32_t*)&h0, *(uint32_t*)&h1);
    }
    __syncthreads();

    wmma::fragment<wmma::accumulator, 16, 16, 16, float> acc00, acc01, acc10, acc11;
    wmma::fill_fragment(acc00, 0.f); wmma::fill_fragment(acc01, 0.f);
    wmma::fill_fragment(acc10, 0.f); wmma::fill_fragment(acc11, 0.f);

    const __half* a0 = xs + (32 * warp) * G_XLD;
    const __half* a1 = xs + (32 * warp + 16) * G_XLD;
#pragma unroll
    for (int k = 0; k < D_IN; k += 16) {
        wmma::fragment<wmma::matrix_a, 16, 16, 16, __half, wmma::row_major> fa0, fa1;
        wmma::fragment<wmma::matrix_b, 16, 16, 16, __half, wmma::row_major> fb0, fb1;
        wmma::load_matrix_sync(fa0, a0 + k, G_XLD);
        wmma::load_matrix_sync(fa1, a1 + k, G_XLD);
        wmma::load_matrix_sync(fb0, ws + k * D_HID, D_HID);
        wmma::load_matrix_sync(fb1, ws + k * D_HID + 16, D_HID);
        wmma::mma_sync(acc00, fa0, fb0, acc00);
        wmma::mma_sync(acc01, fa0, fb1, acc01);
        wmma::mma_sync(acc10, fa1, fb0, acc10);
        wmma::mma_sync(acc11, fa1, fb1, acc11);
    }
    __syncthreads();

    wmma::store_matrix_sync(ys + (32 * warp) * 32,           acc00, 32, wmma::mem_row_major);
    wmma::store_matrix_sync(ys + (32 * warp) * 32 + 16,      acc01, 32, wmma::mem_row_major);
    wmma::store_matrix_sync(ys + (32 * warp + 16) * 32,      acc10, 32, wmma::mem_row_major);
    wmma::store_matrix_sync(ys + (32 * warp + 16) * 32 + 16, acc11, 32, wmma::mem_row_major);
    __syncthreads();

    for (int i = tid; i < G_TR * 8; i += 256) {
        int r = i >> 3, c4 = i & 7;
        const int row = row0 + r;
        if (row < N) {
            float4 v = *(const float4*)(ys + r * 32 + c4 * 4);
            __half2 h0 = __float22half2_rn(make_float2(v.x, v.y));
            __half2 h1 = __float22half2_rn(make_float2(v.z, v.w));
            *(uint2*)(Y + (size_t)row * D_HID + c4 * 4) =
                make_uint2(*(uint32_t*)&h0, *(uint32_t*)&h1);
        }
    }
}

// ---------------------------------------------------------------------------
// Degree counting + per-pair rank capture (counters pre-zeroed by prev call)
// ---------------------------------------------------------------------------
__global__ void degree_rank_kernel(const int* __restrict__ nidx,
                                   const int* __restrict__ eidx,
                                   int* __restrict__ cn, int* __restrict__ ce,
                                   unsigned short* __restrict__ rank_n,
                                   unsigned short* __restrict__ rank_e, int n) {
    int i = blockIdx.x * blockDim.x + threadIdx.x;
    if (i < n) {
        rank_n[i] = (unsigned short)atomicAdd(cn + nidx[i], 1);
        rank_e[i] = (unsigned short)atomicAdd(ce + eidx[i], 1);
    }
}

// ---------------------------------------------------------------------------
// Combined block scan + fused 1/deg
// ---------------------------------------------------------------------------
__global__ void scan_block2(const int* __restrict__ cnt_n, int* __restrict__ off_n,
                            int* __restrict__ aux_n, float* __restrict__ dinv,
                            const int* __restrict__ cnt_e, int* __restrict__ off_e,
                            int* __restrict__ aux_e, float* __restrict__ binv) {
    __shared__ int sm[1024];
    const int b = blockIdx.x;
    const int* in;  int* out; int* aux; float* inv; int n; int bb;
    if (b < NB_N) { in = cnt_n; out = off_n; aux = aux_n; inv = dinv; n = N_NODES; bb = b; }
    else          { in = cnt_e; out = off_e; aux = aux_e; inv = binv; n = N_EDGES; bb = b - NB_N; }

    const int tid = threadIdx.x;
    const int i = bb * 1024 + tid;
    int v = (i < n) ? in[i] : 0;
    if (i < n) inv[i] = (v > 0) ? (1.0f / (float)v) : 0.0f;
    sm[tid] = v;
    __syncthreads();
#pragma unroll
    for (int o = 1; o < 1024; o <<= 1) {
        int t = (tid >= o) ? sm[tid - o] : 0;
        __syncthreads();
        sm[tid] += t;
        __syncthreads();
    }
    if (i < n) out[i] = sm[tid] - v;
    if (tid == 1023) aux[bb] = sm[1023];
}

// Add-pass with inline aux scan
__global__ void scan_add2(int* __restrict__ off_n, const int* __restrict__ aux_n,
                          int* __restrict__ off_e, const int* __restrict__ aux_e) {
    __shared__ int sm[128];
    const int b = blockIdx.x;
    const int t = threadIdx.x;
    const int* aux; int* off; int n; int bb; int nb;
    if (b < NB_N) { aux = aux_n; off = off_n; n = N_NODES; bb = b; nb = NB_N; }
    else          { aux = aux_e; off = off_e; n = N_EDGES; bb = b - NB_N; nb = NB_E; }

    if (t < 128) sm[t] = (t < nb) ? aux[t] : 0;
    __syncthreads();
#pragma unroll
    for (int o = 1; o < 128; o <<= 1) {
        int v = (t < 128 && t >= o) ? sm[t - o] : 0;
        __syncthreads();
        if (t < 128) sm[t] += v;
        __syncthreads();
    }
    const int add = (bb == 0) ? 0 : sm[bb - 1];
    const int i = bb * 1024 + t;
    if (i < n) off[i] += add;
    if (i == 0 && bb == 0) off[n] = N_INC;
}

// ---------------------------------------------------------------------------
// CSR fill — atomic-free; adj_n entries are u16 edge ids
// ---------------------------------------------------------------------------
__global__ void fill_csr(const int* __restrict__ nidx, const int* __restrict__ eidx,
                         const int* __restrict__ off_n, const int* __restrict__ off_e,
                         const unsigned short* __restrict__ rank_n,
                         const unsigned short* __restrict__ rank_e,
                         unsigned short* __restrict__ adj_n, int* __restrict__ adj_e,
                         int n) {
    int i = blockIdx.x * blockDim.x + threadIdx.x;
    if (i < n) {
        int v = nidx[i], e = eidx[i];
        adj_n[__ldg(off_n + v) + (int)rank_n[i]] = (unsigned short)e;
        adj_e[__ldg(off_e + e) + (int)rank_e[i]] = v;
    }
}

// ---------------------------------------------------------------------------
// fp16 CSR gather (validated R13 16-batch loop), index type templated.
// MODE 0: dst = half(scale*sum)   MODE 1: dst = half(relu(scale*sum + bias))
// ---------------------------------------------------------------------------
__device__ __forceinline__ void acc8(float2 a[4], uint4 v) {
    float2 f0 = __half22float2(*(const __half2*)&v.x);
    float2 f1 = __half22float2(*(const __half2*)&v.y);
    float2 f2 = __half22float2(*(const __half2*)&v.z);
    float2 f3 = __half22float2(*(const __half2*)&v.w);
    a[0].x += f0.x; a[0].y += f0.y;
    a[1].x += f1.x; a[1].y += f1.y;
    a[2].x += f2.x; a[2].y += f2.y;
    a[3].x += f3.x; a[3].y += f3.y;
}

template <int MODE, typename IdxT>
__global__ void gather_kernel(const int* __restrict__ off,
                              const IdxT* __restrict__ adj,
                              const __half* __restrict__ src,
                              const float* __restrict__ scale,
                              const float* __restrict__ bias,
                              __half* __restrict__ dst, int nrows) {
    const int row  = (blockIdx.x * blockDim.x + threadIdx.x) >> 5;
    const int lane = threadIdx.x & 31;
    if (row >= nrows) return;
    const int r = lane >> 2;
    const int q = lane & 3;

    const int s = off[row], e = off[row + 1];
    float2 a[4] = {{0.f,0.f},{0.f,0.f},{0.f,0.f},{0.f,0.f}};
    int j = s;
    for (; j + 16 <= e; j += 16) {
        int m0 = (int)adj[j + r];
        int m1 = (int)adj[j + 8 + r];
        uint4 v0 = *(const uint4*)(src + (size_t)m0 * D_HID + q * 8);
        uint4 v1 = *(const uint4*)(src + (size_t)m1 * D_HID + q * 8);
        acc8(a, v0); acc8(a, v1);
    }
    for (; j < e; j += 8) {
        if (j + r < e) {
            int m = (int)adj[j + r];
            uint4 v = *(const uint4*)(src + (size_t)m * D_HID + q * 8);
            acc8(a, v);
        }
    }
#pragma unroll
    for (int o = 4; o <= 16; o <<= 1) {
#pragma unroll
        for (int i = 0; i < 4; i++) {
            a[i].x += __shfl_xor_sync(0xffffffffu, a[i].x, o);
            a[i].y += __shfl_xor_sync(0xffffffffu, a[i].y, o);
        }
    }

    if (r == 0) {
        const float f = scale[row];
        uint4 pk;
        if (MODE == 0) {
            __half2 h0 = __float22half2_rn(make_float2(a[0].x * f, a[0].y * f));
            __half2 h1 = __float22half2_rn(make_float2(a[1].x * f, a[1].y * f));
            __half2 h2 = __float22half2_rn(make_float2(a[2].x * f, a[2].y * f));
            __half2 h3 = __float22half2_rn(make_float2(a[3].x * f, a[3].y * f));
            pk = make_uint4(*(uint32_t*)&h0, *(uint32_t*)&h1,
                            *(uint32_t*)&h2, *(uint32_t*)&h3);
        } else {
            float4 b0 = *(const float4*)(bias + q * 8);
            float4 b1 = *(const float4*)(bias + q * 8 + 4);
            float z0 = fmaxf(a[0].x * f + b0.x, 0.f);
            float z1 = fmaxf(a[0].y * f + b0.y, 0.f);
            float z2 = fmaxf(a[1].x * f + b0.z, 0.f);
            float z3 = fmaxf(a[1].y * f + b0.w, 0.f);
            float z4 = fmaxf(a[2].x * f + b1.x, 0.f);
            float z5 = fmaxf(a[2].y * f + b1.y, 0.f);
            float z6 = fmaxf(a[3].x * f + b1.z, 0.f);
            float z7 = fmaxf(a[3].y * f + b1.w, 0.f);
            __half2 h0 = __float22half2_rn(make_float2(z0, z1));
            __half2 h1 = __float22half2_rn(make_float2(z2, z3));
            __half2 h2 = __float22half2_rn(make_float2(z4, z5));
            __half2 h3 = __float22half2_rn(make_float2(z6, z7));
            pk = make_uint4(*(uint32_t*)&h0, *(uint32_t*)&h1,
                            *(uint32_t*)&h2, *(uint32_t*)&h3);
        }
        *(uint4*)(dst + (size_t)row * D_HID + q * 8) = pk;
    }
}

// ---------------------------------------------------------------------------
// Fused final: fp16 node-gather + @W2 + b2 + log_softmax.
// ALSO re-zeroes the degree counters for the next invocation (before any
// early return — grid has 3.2M threads, covers both counter arrays).
// ---------------------------------------------------------------------------
__global__ void gather_w2_logsoftmax(const int* __restrict__ off,
                                     const unsigned short* __restrict__ adj,
                                     const __half* __restrict__ src,
                                     const float* __restrict__ dinv,
                                     const float* __restrict__ W2,
                                     const float* __restrict__ b2,
                                     float* __restrict__ out, int nrows,
                                     int* __restrict__ cn, int* __restrict__ ce) {
    // re-zero counters for next call (deterministic across replays)
    {
        const int g = blockIdx.x * blockDim.x + threadIdx.x;
        if (g < N_NODES) cn[g] = 0;
        if (g < N_EDGES) ce[g] = 0;
    }

    __shared__ float w2s[D_HID * N_CLASSES];
    __shared__ float b2s[N_CLASSES];
    {
        const int t = threadIdx.x;
        for (int i = t; i < D_HID * N_CLASSES; i += blockDim.x) w2s[i] = W2[i];
        if (t < N_CLASSES) b2s[t] = b2[t];
    }
    __syncthreads();

    const int row  = (blockIdx.x * blockDim.x + threadIdx.x) >> 5;
    const int lane = threadIdx.x & 31;
    if (row >= nrows) return;
    const int r = lane >> 2;
    const int q = lane & 3;

    const int s = off[row], e = off[row + 1];
    float2 a[4] = {{0.f,0.f},{0.f,0.f},{0.f,0.f},{0.f,0.f}};
    int j = s;
    for (; j + 16 <= e; j += 16) {
        int m0 = (int)adj[j + r];
        int m1 = (int)adj[j + 8 + r];
        uint4 v0 = *(const uint4*)(src + (size_t)m0 * D_HID + q * 8);
        uint4 v1 = *(const uint4*)(src + (size_t)m1 * D_HID + q * 8);
        acc8(a, v0); acc8(a, v1);
    }
    for (; j < e; j += 8) {
        if (j + r < e) {
            int m = (int)adj[j + r];
            uint4 v = *(const uint4*)(src + (size_t)m * D_HID + q * 8);
            acc8(a, v);
        }
    }
#pragma unroll
    for (int o = 4; o <= 16; o <<= 1) {
#pragma unroll
        for (int i = 0; i < 4; i++) {
            a[i].x += __shfl_xor_sync(0xffffffffu, a[i].x, o);
            a[i].y += __shfl_xor_sync(0xffffffffu, a[i].y, o);
        }
    }

    const float di = dinv[row];
#pragma unroll
    for (int i = 0; i < 4; i++) { a[i].x *= di; a[i].y *= di; }

    float z0 = 0.f, z1 = 0.f;
#pragma unroll
    for (int k = 0; k < D_HID; k++) {
        const int idx = k & 7;
        float comp = (idx & 1) ? a[idx >> 1].y : a[idx >> 1].x;
        float ak = __shfl_sync(0xffffffffu, comp, k >> 3);
        z0 += ak * w2s[k * N_CLASSES + lane];
        if (lane < N_CLASSES - 32) z1 += ak * w2s[k * N_CLASSES + 32 + lane];
    }
    z0 += b2s[lane];
    z1 = (lane < N_CLASSES - 32) ? (z1 + b2s[32 + lane]) : -1e30f;

    float m = fmaxf(z0, z1);
#pragma unroll
    for (int o = 16; o; o >>= 1) m = fmaxf(m, __shfl_xor_sync(0xffffffffu, m, o));
    float ex = __expf(z0 - m) + ((lane < N_CLASSES - 32) ? __expf(z1 - m) : 0.f);
#pragma unroll
    for (int o = 16; o; o >>= 1) ex += __shfl_xor_sync(0xffffffffu, ex, o);
    const float lse = __logf(ex) + m;

    out[(size_t)row * N_CLASSES + lane] = z0 - lse;
    if (lane < N_CLASSES - 32)
        out[(size_t)row * N_CLASSES + 32 + lane] = z1 - lse;
}

// ---------------------------------------------------------------------------
// Launch — single stream, 8 kernels (no memsets; counters re-zeroed by final)
// ---------------------------------------------------------------------------
extern "C" void kernel_launch(void* const* d_in, const int* in_sizes, int n_in,
                              void* d_out, int out_size) {
    const float* x    = (const float*)d_in[0];
    const int*   nidx = (const int*)d_in[1];
    const int*   eidx = (const int*)d_in[2];
    const float* W1   = (const float*)d_in[3];
    const float* b1   = (const float*)d_in[4];
    const float* W2   = (const float*)d_in[5];
    const float* b2   = (const float*)d_in[6];
    float* out = (float*)d_out;

    __half *xw, *ef, *h1;
    float *dinv, *binv;
    int *cnt_n, *cnt_e, *off_n, *off_e, *adj_e, *aux_n, *aux_e;
    unsigned short *adj_n, *rank_n, *rank_e;
    cudaGetSymbolAddress((void**)&xw,     g_xw);
    cudaGetSymbolAddress((void**)&ef,     g_ef);
    cudaGetSymbolAddress((void**)&h1,     g_h1);
    cudaGetSymbolAddress((void**)&dinv,   g_dinv);
    cudaGetSymbolAddress((void**)&binv,   g_binv);
    cudaGetSymbolAddress((void**)&cnt_n,  g_cnt_n);
    cudaGetSymbolAddress((void**)&cnt_e,  g_cnt_e);
    cudaGetSymbolAddress((void**)&off_n,  g_off_n);
    cudaGetSymbolAddress((void**)&off_e,  g_off_e);
    cudaGetSymbolAddress((void**)&adj_n,  g_adj_n);
    cudaGetSymbolAddress((void**)&adj_e,  g_adj_e);
    cudaGetSymbolAddress((void**)&rank_n, g_rank_n);
    cudaGetSymbolAddress((void**)&rank_e, g_rank_e);
    cudaGetSymbolAddress((void**)&aux_n,  g_aux_n);
    cudaGetSymbolAddress((void**)&aux_e,  g_aux_e);

    cudaFuncSetAttribute(gemm1_kernel,
                         cudaFuncAttributeMaxDynamicSharedMemorySize, G_SMEM);

    // 1: gemm1
    gemm1_kernel<<<(N_NODES + G_TR - 1) / G_TR, 256, G_SMEM>>>(x, W1, xw, N_NODES);

    // 2-5: degrees + CSR build (counters pre-zeroed by previous call / load)
    degree_rank_kernel<<<(N_INC + 255) / 256, 256>>>(nidx, eidx, cnt_n, cnt_e,
                                                     rank_n, rank_e, N_INC);
    scan_block2<<<NB_N + NB_E, 1024>>>(cnt_n, off_n, aux_n, dinv,
                                       cnt_e, off_e, aux_e, binv);
    scan_add2<<<NB_N + NB_E, 1024>>>(off_n, aux_n, off_e, aux_e);
    fill_csr<<<(N_INC + 255) / 256, 256>>>(nidx, eidx, off_n, off_e,
                                           rank_n, rank_e, adj_n, adj_e, N_INC);

    // 6-7: layer 1
    gather_kernel<0, int><<<(N_EDGES + 7) / 8, 256>>>(off_e, adj_e, xw, binv,
                                                      nullptr, ef, N_EDGES);
    gather_kernel<1, unsigned short><<<(N_NODES + 7) / 8, 256>>>(off_n, adj_n, ef,
                                                                 dinv, b1, h1, N_NODES);

    // 8-9: layer 2 (aggregate in hidden space; W2 post-aggregation) + counter re-zero
    gather_kernel<0, int><<<(N_EDGES + 7) / 8, 256>>>(off_e, adj_e, h1, binv,
                                                      nullptr, ef, N_EDGES);
    gather_w2_logsoftmax<<<(N_NODES + 7) / 8, 256>>>(off_n, adj_n, ef, dinv, W2, b2,
                                                     out, N_NODES, cnt_n, cnt_e);
}